// round 3
// baseline (speedup 1.0000x reference)
#include <cuda_runtime.h>
#include <cstdint>

// PolarToCartesianGrid: batched scatter-add of polar intensities into a
// cartesian voxel grid (fixed int32 index map, all in-bounds).
//
// R3 strategy: single-stream software pipeline.
//   17 kernels on the capture stream. Kernel k:
//     - blocks [0, SB)        : scatter batch k-1 (k>0) into slab k-1
//     - blocks [SB, SB+ZB)    : zero slab k (k<batches) with float4 stores
//   zero(k) -> scatter(k) ordering comes free from same-stream kernel order;
//   within kernel k the two halves touch DIFFERENT slabs, so they overlap.
//   Scatter(k-1) atomics land on lines kernel k-1 just zeroed (32.75MB slab
//   << L2), so the atomic read-modify-write stays in L2.

__global__ void pipe_kernel(const float* __restrict__ polar_b,   // batch k-1 or null
                            const int*   __restrict__ vidx,
                            float*       __restrict__ scat_slab, // slab k-1 or null
                            float*       __restrict__ zero_slab, // slab k   or null
                            int n_cells, int scat_blocks, long long n_vox)
{
    if ((int)blockIdx.x < scat_blocks) {
        // ---------------- scatter half: warp-aggregated atomics ------------
        const int cell = blockIdx.x * blockDim.x + threadIdx.x;
        if (cell >= n_cells) return;
        const unsigned FULL = 0xFFFFFFFFu;
        const int lane = threadIdx.x & 31;

        const int idx = vidx[cell];
        float v = __ldg(polar_b + cell);

        const unsigned peers = __match_any_sync(FULL, idx);
        const int rank = __popc(peers & ((1u << lane) - 1u));
        // rank-doubling segmented reduction over the peer group.
        // __fns(mask, lane, n): lane of n-th set bit from 'lane' (own bit=1),
        // 0xFFFFFFFF if absent.
        const unsigned s1  = __fns(peers, lane, 2);
        const unsigned s2  = __fns(peers, lane, 3);
        const unsigned s4  = __fns(peers, lane, 5);
        const unsigned s8  = __fns(peers, lane, 9);
        const unsigned s16 = __fns(peers, lane, 17);
        float t;
        t = __shfl_sync(FULL, v, s1  & 31); if (s1  < 32) v += t;
        t = __shfl_sync(FULL, v, s2  & 31); if (s2  < 32) v += t;
        t = __shfl_sync(FULL, v, s4  & 31); if (s4  < 32) v += t;
        t = __shfl_sync(FULL, v, s8  & 31); if (s8  < 32) v += t;
        t = __shfl_sync(FULL, v, s16 & 31); if (s16 < 32) v += t;

        if (rank == 0) atomicAdd(scat_slab + idx, v);
    } else {
        // ---------------- zero half: float4 grid-stride stores -------------
        if (zero_slab == nullptr) return;
        float4* dst = (float4*)zero_slab;
        const long long n4 = n_vox >> 2;                 // n_vox % 4 == 0
        const int zid = ((int)blockIdx.x - scat_blocks) * blockDim.x + threadIdx.x;
        const long long stride = (long long)(gridDim.x - scat_blocks) * blockDim.x;
        const float4 z = make_float4(0.f, 0.f, 0.f, 0.f);
        for (long long i = zid; i < n4; i += stride) dst[i] = z;
    }
}

extern "C" void kernel_launch(void* const* d_in, const int* in_sizes, int n_in,
                              void* d_out, int out_size)
{
    const float* polar = (const float*)d_in[0];            // [B,1,El,R,Az] f32
    const int*   vidx  = (const int*)d_in[1];              // [El*R*Az] int32
    float*       out   = (float*)d_out;                    // [B,1,Z,Y,X] f32

    const int n_cells   = in_sizes[1];                     // 1,048,576
    const int batches   = in_sizes[0] / n_cells;           // 16
    const long long n_vox = (long long)out_size / batches; // 8,192,000

    const int threads = 256;
    const int SB = (n_cells + threads - 1) / threads;      // 4096 scatter blocks
    const int ZB = 2048;                                   // zeroing blocks

    for (int k = 0; k <= batches; ++k) {
        const bool has_scat = (k > 0);
        const bool has_zero = (k < batches);
        const int  sb   = has_scat ? SB : 0;
        const int  grid = sb + (has_zero ? ZB : 0);
        pipe_kernel<<<grid, threads>>>(
            has_scat ? polar + (size_t)(k - 1) * n_cells : nullptr,
            vidx,
            has_scat ? out + (long long)(k - 1) * n_vox : nullptr,
            has_zero ? out + (long long)k * n_vox       : nullptr,
            n_cells, sb, n_vox);
    }
}